// round 3
// baseline (speedup 1.0000x reference)
#include <cuda_runtime.h>
#include <cuda_bf16.h>
#include <math.h>

#define NN 100000
#define NE 1600000
#define F  128
#define OUTD 32
#define SCAN_B 1024
#define NBLK_SCAN 98   // ceil(100000/1024)

// ---------------- device scratch (no allocations allowed) ----------------
static __device__ int   g_deg[NN];
static __device__ int   g_incl[NN];
static __device__ int   g_bsum[NBLK_SCAN];
static __device__ int   g_rowstart[NN];
static __device__ int   g_cursor[NN];
static __device__ int   g_col[NE];
static __device__ float g_invdeg[NN];

static __device__ float g_H1[NN * F];
static __device__ float g_H2[NN * F];
static __device__ float g_AGG[NN * F];

static __device__ float g_colsum[F];
static __device__ float g_colsq[F];
static __device__ float g_scale[F];
static __device__ float g_shift[F];
static __device__ float g_msum[F];
static __device__ float g_wa[F];

// ---------------- kernels ----------------

__global__ void k_zero() {
    int i = blockIdx.x * blockDim.x + threadIdx.x;
    if (i < NN) g_deg[i] = 0;
    if (i < F) {
        g_colsum[i] = 0.f; g_colsq[i] = 0.f;
        g_msum[i]   = 0.f; g_wa[i]    = 0.f;
    }
}

__global__ void k_hist(const int* __restrict__ dst) {
    int e = blockIdx.x * blockDim.x + threadIdx.x;
    if (e < NE) atomicAdd(&g_deg[dst[e]], 1);
}

__global__ void k_scan_block() {
    __shared__ int s[SCAN_B];
    int t = threadIdx.x;
    int i = blockIdx.x * SCAN_B + t;
    int v = (i < NN) ? g_deg[i] : 0;
    s[t] = v;
    __syncthreads();
    for (int off = 1; off < SCAN_B; off <<= 1) {
        int x = (t >= off) ? s[t - off] : 0;
        __syncthreads();
        s[t] += x;
        __syncthreads();
    }
    if (i < NN) g_incl[i] = s[t];
    if (t == SCAN_B - 1) g_bsum[blockIdx.x] = s[t];
}

__global__ void k_scan_top() {
    if (threadIdx.x == 0 && blockIdx.x == 0) {
        int run = 0;
        for (int b = 0; b < NBLK_SCAN; b++) {
            int x = g_bsum[b];
            g_bsum[b] = run;
            run += x;
        }
    }
}

__global__ void k_scan_finish() {
    int i = blockIdx.x * blockDim.x + threadIdx.x;
    if (i < NN) {
        int d = g_deg[i];
        int start = g_incl[i] - d + g_bsum[i / SCAN_B];
        g_rowstart[i] = start;
        g_cursor[i]   = start;
        g_invdeg[i]   = 1.0f / (float)max(d, 1);
    }
}

__global__ void k_fill(const int* __restrict__ src, const int* __restrict__ dst) {
    int e = blockIdx.x * blockDim.x + threadIdx.x;
    if (e < NE) {
        int pos = atomicAdd(&g_cursor[dst[e]], 1);
        g_col[pos] = src[e];
    }
}

// warp-per-node CSR mean aggregation: AGG[n,:] = invdeg[n] * sum_{s in N(n)} Hin[s,:]
__global__ void k_agg(const float* __restrict__ Hin) {
    int warp = (blockIdx.x * blockDim.x + threadIdx.x) >> 5;
    int lane = threadIdx.x & 31;
    if (warp >= NN) return;
    const float4* H4 = (const float4*)Hin;
    int start = g_rowstart[warp];
    int d     = g_deg[warp];
    float4 acc = make_float4(0.f, 0.f, 0.f, 0.f);
    for (int j = 0; j < d; j++) {
        int s = g_col[start + j];
        float4 v = H4[s * 32 + lane];
        acc.x += v.x; acc.y += v.y; acc.z += v.z; acc.w += v.w;
    }
    float w = g_invdeg[warp];
    acc.x *= w; acc.y *= w; acc.z *= w; acc.w *= w;
    ((float4*)g_AGG)[warp * 32 + lane] = acc;
}

// Hout = relu([X | AGG] @ [Ws;Wn] + b), fused BN-stat accumulation.
// block: 256 threads, tile 128 rows x 128 cols, K = 256 in 16-wide chunks.
__global__ __launch_bounds__(256) void k_gemm(
    const float* __restrict__ X,
    const float* __restrict__ Ws,
    const float* __restrict__ Wn,
    const float* __restrict__ bias,
    float* __restrict__ Hout)
{
    __shared__ float As[16][132];
    __shared__ float Wsh[16][128];
    __shared__ float sColS[128];
    __shared__ float sColQ[128];

    int tid = threadIdx.x;
    int tx = tid & 15, ty = tid >> 4;
    int row0 = blockIdx.x * 128;

    if (tid < 128) { sColS[tid] = 0.f; sColQ[tid] = 0.f; }

    float acc[8][8];
    #pragma unroll
    for (int i = 0; i < 8; i++)
        #pragma unroll
        for (int j = 0; j < 8; j++) acc[i][j] = 0.f;

    for (int kt = 0; kt < 16; kt++) {
        // load A tile: 128 rows x 16 cols of concat[X, AGG]
        #pragma unroll
        for (int p = 0; p < 2; p++) {
            int rowl = p * 64 + (tid >> 2);
            int c4   = (tid & 3) * 4;
            int ksrc = kt * 16 + c4;
            int grow = row0 + rowl;
            float4 av = make_float4(0.f, 0.f, 0.f, 0.f);
            if (grow < NN) {
                const float* base = (ksrc < 128) ? (X + (size_t)grow * 128 + ksrc)
                                                 : (g_AGG + (size_t)grow * 128 + (ksrc - 128));
                av = *(const float4*)base;
            }
            As[c4 + 0][rowl] = av.x;
            As[c4 + 1][rowl] = av.y;
            As[c4 + 2][rowl] = av.z;
            As[c4 + 3][rowl] = av.w;
        }
        // load W tile: 16 rows (K) x 128 cols of concat[Ws; Wn]
        #pragma unroll
        for (int p = 0; p < 2; p++) {
            int krow = p * 8 + (tid >> 5);
            int nc   = (tid & 31) * 4;
            int k    = kt * 16 + krow;
            const float* base = (k < 128) ? (Ws + (size_t)k * 128 + nc)
                                          : (Wn + (size_t)(k - 128) * 128 + nc);
            *(float4*)&Wsh[krow][nc] = *(const float4*)base;
        }
        __syncthreads();

        #pragma unroll
        for (int k = 0; k < 16; k++) {
            float4 a0 = *(float4*)&As[k][ty * 8];
            float4 a1 = *(float4*)&As[k][ty * 8 + 4];
            float4 w0 = *(float4*)&Wsh[k][tx * 8];
            float4 w1 = *(float4*)&Wsh[k][tx * 8 + 4];
            float ar[8] = {a0.x, a0.y, a0.z, a0.w, a1.x, a1.y, a1.z, a1.w};
            float wr[8] = {w0.x, w0.y, w0.z, w0.w, w1.x, w1.y, w1.z, w1.w};
            #pragma unroll
            for (int i = 0; i < 8; i++)
                #pragma unroll
                for (int j = 0; j < 8; j++)
                    acc[i][j] += ar[i] * wr[j];
        }
        __syncthreads();
    }

    // epilogue: bias + relu + store + BN stats
    float4 b0 = ((const float4*)bias)[tx * 2];
    float4 b1 = ((const float4*)bias)[tx * 2 + 1];
    float bb[8] = {b0.x, b0.y, b0.z, b0.w, b1.x, b1.y, b1.z, b1.w};

    float sj[8], qj[8];
    #pragma unroll
    for (int j = 0; j < 8; j++) { sj[j] = 0.f; qj[j] = 0.f; }

    #pragma unroll
    for (int i = 0; i < 8; i++) {
        int grow = row0 + ty * 8 + i;
        bool valid = (grow < NN);
        float v[8];
        #pragma unroll
        for (int j = 0; j < 8; j++) {
            float x = acc[i][j] + bb[j];
            x = fmaxf(x, 0.f);
            v[j] = x;
            if (valid) { sj[j] += x; qj[j] += x * x; }
        }
        if (valid) {
            float* o = Hout + (size_t)grow * 128 + tx * 8;
            *(float4*)o       = make_float4(v[0], v[1], v[2], v[3]);
            *(float4*)(o + 4) = make_float4(v[4], v[5], v[6], v[7]);
        }
    }
    #pragma unroll
    for (int j = 0; j < 8; j++) {
        atomicAdd(&sColS[tx * 8 + j], sj[j]);
        atomicAdd(&sColQ[tx * 8 + j], qj[j]);
    }
    __syncthreads();
    if (tid < 128) {
        atomicAdd(&g_colsum[tid], sColS[tid]);
        atomicAdd(&g_colsq[tid],  sColQ[tid]);
    }
}

__global__ void k_bnfinal(const float* __restrict__ g, const float* __restrict__ be) {
    int t = threadIdx.x;
    if (t < F) {
        float inv_n = 1.0f / (float)NN;
        float mu  = g_colsum[t] * inv_n;
        float var = g_colsq[t] * inv_n - mu * mu;
        float sc  = g[t] * rsqrtf(var + 1e-5f);
        g_scale[t] = sc;
        g_shift[t] = be[t] - mu * sc;
        g_colsum[t] = 0.f;   // ready for next gemm
        g_colsq[t]  = 0.f;
    }
}

__global__ void k_bnapply(float* __restrict__ H) {
    int i4 = blockIdx.x * blockDim.x + threadIdx.x;  // float4 index
    if (i4 >= NN * 32) return;
    int c4 = (i4 & 31) * 4;
    float4 v = ((float4*)H)[i4];
    float4 sc = *(const float4*)&g_scale[c4];
    float4 sh = *(const float4*)&g_shift[c4];
    v.x = fmaxf(v.x * sc.x + sh.x, 0.f);
    v.y = fmaxf(v.y * sc.y + sh.y, 0.f);
    v.z = fmaxf(v.z * sc.z + sh.z, 0.f);
    v.w = fmaxf(v.w * sc.w + sh.w, 0.f);
    ((float4*)H)[i4] = v;
}

// msum += column sums of H over all nodes
__global__ void k_nodesum(const float* __restrict__ H) {
    int t = threadIdx.x;           // 0..127 = column
    int r0 = blockIdx.x * 400;
    float s = 0.f;
    for (int r = 0; r < 400; r++) {
        int row = r0 + r;
        if (row < NN) s += H[(size_t)row * 128 + t];
    }
    atomicAdd(&g_msum[t], s);
}

// wa += sum_e invdeg[dst[e]] * H[src[e], :]
__global__ void k_edgesum(const int* __restrict__ src, const int* __restrict__ dst,
                          const float* __restrict__ H) {
    __shared__ float sw[128];
    int tid = threadIdx.x;
    if (tid < 128) sw[tid] = 0.f;
    __syncthreads();
    int lane = tid & 31;
    int warp = (blockIdx.x * blockDim.x + tid) >> 5;
    int nwarps = (gridDim.x * blockDim.x) >> 5;
    const float4* H4 = (const float4*)H;
    float4 acc = make_float4(0.f, 0.f, 0.f, 0.f);
    for (int e = warp; e < NE; e += nwarps) {
        int s = src[e];
        float w = g_invdeg[dst[e]];
        float4 v = H4[s * 32 + lane];
        acc.x += w * v.x; acc.y += w * v.y; acc.z += w * v.z; acc.w += w * v.w;
    }
    atomicAdd(&sw[lane * 4 + 0], acc.x);
    atomicAdd(&sw[lane * 4 + 1], acc.y);
    atomicAdd(&sw[lane * 4 + 2], acc.z);
    atomicAdd(&sw[lane * 4 + 3], acc.w);
    __syncthreads();
    if (tid < 128) atomicAdd(&g_wa[tid], sw[tid]);
}

// hg = (msum/N)@Ws2 + (wa/N)@Wn2 + b2 ; out = softmax(hg)
__global__ void k_final(const float* __restrict__ Ws2, const float* __restrict__ Wn2,
                        const float* __restrict__ b2, float* __restrict__ out) {
    int j = threadIdx.x;  // 0..31
    float inv_n = 1.0f / (float)NN;
    float acc = b2[j];
    for (int k = 0; k < 128; k++) {
        acc += (g_msum[k] * inv_n) * Ws2[k * 32 + j]
             + (g_wa[k]   * inv_n) * Wn2[k * 32 + j];
    }
    // warp softmax over 32 lanes
    float m = acc;
    #pragma unroll
    for (int off = 16; off > 0; off >>= 1)
        m = fmaxf(m, __shfl_xor_sync(0xffffffffu, m, off));
    float e = expf(acc - m);
    float s = e;
    #pragma unroll
    for (int off = 16; off > 0; off >>= 1)
        s += __shfl_xor_sync(0xffffffffu, s, off);
    out[j] = e / s;
}

// ---------------- host ----------------

extern "C" void kernel_launch(void* const* d_in, const int* in_sizes, int n_in,
                              void* d_out, int out_size) {
    const float* features = (const float*)d_in[0];
    const int*   src      = (const int*)  d_in[1];
    const int*   dst      = (const int*)  d_in[2];
    const float* Ws0 = (const float*)d_in[3];
    const float* Wn0 = (const float*)d_in[4];
    const float* b0  = (const float*)d_in[5];
    const float* Ws1 = (const float*)d_in[6];
    const float* Wn1 = (const float*)d_in[7];
    const float* b1  = (const float*)d_in[8];
    const float* Ws2 = (const float*)d_in[9];
    const float* Wn2 = (const float*)d_in[10];
    const float* b2  = (const float*)d_in[11];
    const float* g0  = (const float*)d_in[12];
    const float* be0 = (const float*)d_in[13];
    const float* g1  = (const float*)d_in[14];
    const float* be1 = (const float*)d_in[15];
    float* out = (float*)d_out;

    float* H1  = nullptr; cudaGetSymbolAddress((void**)&H1,  g_H1);
    float* H2  = nullptr; cudaGetSymbolAddress((void**)&H2,  g_H2);

    // --- CSR build + zero accumulators ---
    k_zero<<<(NN + 255) / 256, 256>>>();
    k_hist<<<NE / 256, 256>>>(dst);
    k_scan_block<<<NBLK_SCAN, SCAN_B>>>();
    k_scan_top<<<1, 1>>>();
    k_scan_finish<<<(NN + 255) / 256, 256>>>();
    k_fill<<<NE / 256, 256>>>(src, dst);

    // --- layer 0 ---
    k_agg<<<NN / 8, 256>>>(features);
    k_gemm<<<(NN + 127) / 128, 256>>>(features, Ws0, Wn0, b0, H1);
    k_bnfinal<<<1, 128>>>(g0, be0);
    k_bnapply<<<(NN * 32 + 255) / 256, 256>>>(H1);

    // --- layer 1 ---
    k_agg<<<NN / 8, 256>>>(H1);
    k_gemm<<<(NN + 127) / 128, 256>>>(H1, Ws1, Wn1, b1, H2);
    k_bnfinal<<<1, 128>>>(g1, be1);
    k_bnapply<<<(NN * 32 + 255) / 256, 256>>>(H2);

    // --- layer 2 (collapsed through the final mean) ---
    k_nodesum<<<(NN + 399) / 400, 128>>>(H2);
    k_edgesum<<<1024, 256>>>(src, dst, H2);
    k_final<<<1, 32>>>(Ws2, Wn2, b2, out);
}

// round 4
// speedup vs baseline: 1.2425x; 1.2425x over previous
#include <cuda_runtime.h>
#include <cuda_bf16.h>
#include <math.h>
#include <stdint.h>

#define NN 100000
#define NE 1600000
#define F  128
#define OUTD 32
#define SCAN_B 1024
#define NBLK_SCAN 98   // ceil(100000/1024)

// ---------------- device scratch (no allocations allowed) ----------------
static __device__ int   g_deg[NN];
static __device__ int   g_incl[NN];
static __device__ int   g_bsum[NBLK_SCAN];
static __device__ int   g_rowstart[NN];
static __device__ int   g_cursor[NN];
static __device__ int   g_col[NE];
static __device__ float g_invdeg[NN];
static __device__ float g_cw[NN];          // c[s] = sum over out-edges of invdeg[dst]

static __device__ float g_H1[NN * F];
static __device__ float g_H2[NN * F];
static __device__ float g_AGG[NN * F];

static __device__ float g_colsum[F];
static __device__ float g_colsq[F];
static __device__ float g_scale[F];
static __device__ float g_shift[F];
static __device__ float g_msum[F];
static __device__ float g_wa[F];

// ---------------- helpers ----------------

__device__ __forceinline__ uint32_t f2tf32(float x) {
    uint32_t u;
    asm("cvt.rna.tf32.f32 %0, %1;" : "=r"(u) : "f"(x));
    return u;
}

__device__ __forceinline__ void mma_tf32(float c[4], const uint32_t a[4], const uint32_t b[2]) {
    asm volatile(
        "mma.sync.aligned.m16n8k8.row.col.f32.tf32.tf32.f32 "
        "{%0,%1,%2,%3}, {%4,%5,%6,%7}, {%8,%9}, {%0,%1,%2,%3};"
        : "+f"(c[0]), "+f"(c[1]), "+f"(c[2]), "+f"(c[3])
        : "r"(a[0]), "r"(a[1]), "r"(a[2]), "r"(a[3]), "r"(b[0]), "r"(b[1]));
}

// ---------------- CSR build ----------------

__global__ void k_zero() {
    int i = blockIdx.x * blockDim.x + threadIdx.x;
    if (i < NN) { g_deg[i] = 0; g_cw[i] = 0.f; }
    if (i < F) {
        g_colsum[i] = 0.f; g_colsq[i] = 0.f;
        g_msum[i]   = 0.f; g_wa[i]    = 0.f;
    }
}

__global__ void k_hist(const int* __restrict__ dst) {
    int e = blockIdx.x * blockDim.x + threadIdx.x;
    if (e < NE) atomicAdd(&g_deg[dst[e]], 1);
}

__global__ void k_scan_block() {
    __shared__ int s[SCAN_B];
    int t = threadIdx.x;
    int i = blockIdx.x * SCAN_B + t;
    int v = (i < NN) ? g_deg[i] : 0;
    s[t] = v;
    __syncthreads();
    for (int off = 1; off < SCAN_B; off <<= 1) {
        int x = (t >= off) ? s[t - off] : 0;
        __syncthreads();
        s[t] += x;
        __syncthreads();
    }
    if (i < NN) g_incl[i] = s[t];
    if (t == SCAN_B - 1) g_bsum[blockIdx.x] = s[t];
}

__global__ void k_scan_top() {   // 1 block, 128 threads: exclusive scan of g_bsum
    __shared__ int ws[4];
    int t = threadIdx.x;
    int lane = t & 31, w = t >> 5;
    int v = (t < NBLK_SCAN) ? g_bsum[t] : 0;
    int x = v;
    #pragma unroll
    for (int off = 1; off < 32; off <<= 1) {
        int y = __shfl_up_sync(0xffffffffu, x, off);
        if (lane >= off) x += y;
    }
    if (lane == 31) ws[w] = x;
    __syncthreads();
    int add = 0;
    #pragma unroll
    for (int i = 0; i < 4; i++) if (i < w) add += ws[i];
    if (t < NBLK_SCAN) g_bsum[t] = x + add - v;   // exclusive
}

__global__ void k_scan_finish() {
    int i = blockIdx.x * blockDim.x + threadIdx.x;
    if (i < NN) {
        int d = g_deg[i];
        int start = g_incl[i] - d + g_bsum[i / SCAN_B];
        g_rowstart[i] = start;
        g_cursor[i]   = start;
        g_invdeg[i]   = 1.0f / (float)max(d, 1);
    }
}

__global__ void k_fill(const int* __restrict__ src, const int* __restrict__ dst) {
    int e = blockIdx.x * blockDim.x + threadIdx.x;
    if (e < NE) {
        int pos = atomicAdd(&g_cursor[dst[e]], 1);
        g_col[pos] = src[e];
    }
}

__global__ void k_cw(const int* __restrict__ src, const int* __restrict__ dst) {
    int e = blockIdx.x * blockDim.x + threadIdx.x;
    if (e < NE) atomicAdd(&g_cw[src[e]], g_invdeg[dst[e]]);
}

// ---------------- aggregation ----------------

// warp-per-node CSR mean aggregation: AGG[n,:] = invdeg[n] * sum_{s in N(n)} Hin[s,:]
__global__ void k_agg(const float* __restrict__ Hin) {
    int warp = (blockIdx.x * blockDim.x + threadIdx.x) >> 5;
    int lane = threadIdx.x & 31;
    if (warp >= NN) return;
    const float4* H4 = (const float4*)Hin;
    int start = g_rowstart[warp];
    int d     = g_deg[warp];
    float4 acc = make_float4(0.f, 0.f, 0.f, 0.f);
    int j = 0;
    for (; j + 4 <= d; j += 4) {
        int s0 = g_col[start + j];
        int s1 = g_col[start + j + 1];
        int s2 = g_col[start + j + 2];
        int s3 = g_col[start + j + 3];
        float4 v0 = H4[s0 * 32 + lane];
        float4 v1 = H4[s1 * 32 + lane];
        float4 v2 = H4[s2 * 32 + lane];
        float4 v3 = H4[s3 * 32 + lane];
        acc.x += v0.x + v1.x + v2.x + v3.x;
        acc.y += v0.y + v1.y + v2.y + v3.y;
        acc.z += v0.z + v1.z + v2.z + v3.z;
        acc.w += v0.w + v1.w + v2.w + v3.w;
    }
    for (; j < d; j++) {
        int s = g_col[start + j];
        float4 v = H4[s * 32 + lane];
        acc.x += v.x; acc.y += v.y; acc.z += v.z; acc.w += v.w;
    }
    float w = g_invdeg[warp];
    acc.x *= w; acc.y *= w; acc.z *= w; acc.w *= w;
    ((float4*)g_AGG)[warp * 32 + lane] = acc;
}

// ---------------- tf32 tensor-core GEMM ----------------
// Hout = relu([X | AGG] @ [Ws;Wn] + b), fused BN-stat accumulation.
// block 256 threads (8 warps). Tile 128(M) x 128(N), K=256 in chunks of 32.
// warp_m = wid>>1 (32-row slice), warp_n = wid&1 (64-col slice).
// mma m16n8k8 tf32; per warp: 2 m-frags x 8 n-frags.

#define AS_LD 36
#define BS_LD 136

__global__ __launch_bounds__(256) void k_gemm(
    const float* __restrict__ X,
    const float* __restrict__ Ws,
    const float* __restrict__ Wn,
    const float* __restrict__ bias,
    float* __restrict__ Hout)
{
    __shared__ float As[128 * AS_LD];   // m-major
    __shared__ float Bs[32 * BS_LD];    // k-major
    __shared__ float sColS[128];
    __shared__ float sColQ[128];

    int tid  = threadIdx.x;
    int lane = tid & 31;
    int wid  = tid >> 5;
    int warp_m = wid >> 1;         // 0..3
    int warp_n = wid & 1;          // 0..1
    int g  = lane >> 2;            // 0..7
    int tg = lane & 3;             // 0..3
    int row0 = blockIdx.x * 128;

    if (tid < 128) { sColS[tid] = 0.f; sColQ[tid] = 0.f; }

    float c[2][8][4];
    #pragma unroll
    for (int mt = 0; mt < 2; mt++)
        #pragma unroll
        for (int nt = 0; nt < 8; nt++)
            #pragma unroll
            for (int r = 0; r < 4; r++) c[mt][nt][r] = 0.f;

    const uint32_t* Asu = (const uint32_t*)As;
    const uint32_t* Bsu = (const uint32_t*)Bs;

    for (int kc = 0; kc < 8; kc++) {
        // ---- load A tile: rows row0..+127, k-cols kc*32..+31 of [X|AGG] ----
        #pragma unroll
        for (int p = 0; p < 4; p++) {
            int id   = tid + p * 256;       // 0..1023 float4 slots
            int arow = id >> 3;
            int ac4  = id & 7;
            int kg   = kc * 32 + ac4 * 4;
            int grow = row0 + arow;
            float4 av = make_float4(0.f, 0.f, 0.f, 0.f);
            if (grow < NN) {
                const float* base = (kg < 128) ? (X + (size_t)grow * 128 + kg)
                                               : (g_AGG + (size_t)grow * 128 + (kg - 128));
                av = *(const float4*)base;
            }
            uint4 tv;
            tv.x = f2tf32(av.x); tv.y = f2tf32(av.y);
            tv.z = f2tf32(av.z); tv.w = f2tf32(av.w);
            *(uint4*)&As[arow * AS_LD + ac4 * 4] = tv;
        }
        // ---- load B tile: k-rows kc*32..+31, n-cols 0..127 of [Ws;Wn] ----
        #pragma unroll
        for (int p = 0; p < 4; p++) {
            int id  = tid + p * 256;
            int bk  = id >> 5;              // 0..31 local k
            int bn4 = id & 31;              // float4 col group
            int kg  = kc * 32 + bk;
            const float* base = (kg < 128) ? (Ws + (size_t)kg * 128 + bn4 * 4)
                                           : (Wn + (size_t)(kg - 128) * 128 + bn4 * 4);
            float4 wv = *(const float4*)base;
            uint4 tv;
            tv.x = f2tf32(wv.x); tv.y = f2tf32(wv.y);
            tv.z = f2tf32(wv.z); tv.w = f2tf32(wv.w);
            *(uint4*)&Bs[bk * BS_LD + bn4 * 4] = tv;
        }
        __syncthreads();

        #pragma unroll
        for (int ks = 0; ks < 4; ks++) {
            int k0 = ks * 8;
            uint32_t a[2][4];
            #pragma unroll
            for (int mt = 0; mt < 2; mt++) {
                int bm = warp_m * 32 + mt * 16;
                a[mt][0] = Asu[(bm + g) * AS_LD + k0 + tg];
                a[mt][1] = Asu[(bm + g + 8) * AS_LD + k0 + tg];
                a[mt][2] = Asu[(bm + g) * AS_LD + k0 + tg + 4];
                a[mt][3] = Asu[(bm + g + 8) * AS_LD + k0 + tg + 4];
            }
            uint32_t b[8][2];
            #pragma unroll
            for (int nt = 0; nt < 8; nt++) {
                int bn = warp_n * 64 + nt * 8 + g;
                b[nt][0] = Bsu[(k0 + tg) * BS_LD + bn];
                b[nt][1] = Bsu[(k0 + tg + 4) * BS_LD + bn];
            }
            #pragma unroll
            for (int mt = 0; mt < 2; mt++)
                #pragma unroll
                for (int nt = 0; nt < 8; nt++)
                    mma_tf32(c[mt][nt], a[mt], b[nt]);
        }
        __syncthreads();
    }

    // ---- epilogue: bias + relu + store + BN stats ----
    #pragma unroll
    for (int mt = 0; mt < 2; mt++) {
        int rA = row0 + warp_m * 32 + mt * 16 + g;
        int rB = rA + 8;
        bool vA = rA < NN, vB = rB < NN;
        #pragma unroll
        for (int nt = 0; nt < 8; nt++) {
            int col = warp_n * 64 + nt * 8 + tg * 2;
            float2 bb = *(const float2*)&bias[col];
            float v0 = fmaxf(c[mt][nt][0] + bb.x, 0.f);
            float v1 = fmaxf(c[mt][nt][1] + bb.y, 0.f);
            float v2 = fmaxf(c[mt][nt][2] + bb.x, 0.f);
            float v3 = fmaxf(c[mt][nt][3] + bb.y, 0.f);
            float s0 = 0.f, s1 = 0.f, q0 = 0.f, q1 = 0.f;
            if (vA) {
                *(float2*)&Hout[(size_t)rA * 128 + col] = make_float2(v0, v1);
                s0 += v0; q0 += v0 * v0; s1 += v1; q1 += v1 * v1;
            }
            if (vB) {
                *(float2*)&Hout[(size_t)rB * 128 + col] = make_float2(v2, v3);
                s0 += v2; q0 += v2 * v2; s1 += v3; q1 += v3 * v3;
            }
            atomicAdd(&sColS[col], s0);
            atomicAdd(&sColS[col + 1], s1);
            atomicAdd(&sColQ[col], q0);
            atomicAdd(&sColQ[col + 1], q1);
        }
    }
    __syncthreads();
    if (tid < 128) {
        atomicAdd(&g_colsum[tid], sColS[tid]);
        atomicAdd(&g_colsq[tid],  sColQ[tid]);
    }
}

// ---------------- BN ----------------

__global__ void k_bnfinal(const float* __restrict__ g, const float* __restrict__ be) {
    int t = threadIdx.x;
    if (t < F) {
        float inv_n = 1.0f / (float)NN;
        float mu  = g_colsum[t] * inv_n;
        float var = g_colsq[t] * inv_n - mu * mu;
        float sc  = g[t] * rsqrtf(var + 1e-5f);
        g_scale[t] = sc;
        g_shift[t] = be[t] - mu * sc;
        g_colsum[t] = 0.f;   // ready for next gemm
        g_colsq[t]  = 0.f;
    }
}

__global__ void k_bnapply(float* __restrict__ H) {
    int i4 = blockIdx.x * blockDim.x + threadIdx.x;  // float4 index
    if (i4 >= NN * 32) return;
    int c4 = (i4 & 31) * 4;
    float4 v = ((float4*)H)[i4];
    float4 sc = *(const float4*)&g_scale[c4];
    float4 sh = *(const float4*)&g_shift[c4];
    v.x = fmaxf(v.x * sc.x + sh.x, 0.f);
    v.y = fmaxf(v.y * sc.y + sh.y, 0.f);
    v.z = fmaxf(v.z * sc.z + sh.z, 0.f);
    v.w = fmaxf(v.w * sc.w + sh.w, 0.f);
    ((float4*)H)[i4] = v;
}

// ---------------- final collapsed layer-2 ----------------

// msum += column sums of H ; wa += sum_s c[s] * H[s,:]
__global__ void k_nodesum(const float* __restrict__ H) {
    int t = threadIdx.x;           // 0..127 = column
    int r0 = blockIdx.x * 400;
    float s = 0.f, w = 0.f;
    for (int r = 0; r < 400; r++) {
        int row = r0 + r;
        if (row < NN) {
            float h = H[(size_t)row * 128 + t];
            float cw = g_cw[row];
            s += h;
            w += cw * h;
        }
    }
    atomicAdd(&g_msum[t], s);
    atomicAdd(&g_wa[t], w);
}

// hg = (msum/N)@Ws2 + (wa/N)@Wn2 + b2 ; out = softmax(hg)
__global__ void k_final(const float* __restrict__ Ws2, const float* __restrict__ Wn2,
                        const float* __restrict__ b2, float* __restrict__ out) {
    int j = threadIdx.x;  // 0..31
    float inv_n = 1.0f / (float)NN;
    float acc = b2[j];
    for (int k = 0; k < 128; k++) {
        acc += (g_msum[k] * inv_n) * Ws2[k * 32 + j]
             + (g_wa[k]   * inv_n) * Wn2[k * 32 + j];
    }
    float m = acc;
    #pragma unroll
    for (int off = 16; off > 0; off >>= 1)
        m = fmaxf(m, __shfl_xor_sync(0xffffffffu, m, off));
    float e = expf(acc - m);
    float s = e;
    #pragma unroll
    for (int off = 16; off > 0; off >>= 1)
        s += __shfl_xor_sync(0xffffffffu, s, off);
    out[j] = e / s;
}

// ---------------- host ----------------

extern "C" void kernel_launch(void* const* d_in, const int* in_sizes, int n_in,
                              void* d_out, int out_size) {
    const float* features = (const float*)d_in[0];
    const int*   src      = (const int*)  d_in[1];
    const int*   dst      = (const int*)  d_in[2];
    const float* Ws0 = (const float*)d_in[3];
    const float* Wn0 = (const float*)d_in[4];
    const float* b0  = (const float*)d_in[5];
    const float* Ws1 = (const float*)d_in[6];
    const float* Wn1 = (const float*)d_in[7];
    const float* b1  = (const float*)d_in[8];
    const float* Ws2 = (const float*)d_in[9];
    const float* Wn2 = (const float*)d_in[10];
    const float* b2  = (const float*)d_in[11];
    const float* g0  = (const float*)d_in[12];
    const float* be0 = (const float*)d_in[13];
    const float* g1  = (const float*)d_in[14];
    const float* be1 = (const float*)d_in[15];
    float* out = (float*)d_out;

    float* H1  = nullptr; cudaGetSymbolAddress((void**)&H1,  g_H1);
    float* H2  = nullptr; cudaGetSymbolAddress((void**)&H2,  g_H2);

    // --- CSR build + zero accumulators ---
    k_zero<<<(NN + 255) / 256, 256>>>();
    k_hist<<<NE / 256, 256>>>(dst);
    k_scan_block<<<NBLK_SCAN, SCAN_B>>>();
    k_scan_top<<<1, 128>>>();
    k_scan_finish<<<(NN + 255) / 256, 256>>>();
    k_fill<<<NE / 256, 256>>>(src, dst);
    k_cw<<<NE / 256, 256>>>(src, dst);

    // --- layer 0 ---
    k_agg<<<NN / 8, 256>>>(features);
    k_gemm<<<(NN + 127) / 128, 256>>>(features, Ws0, Wn0, b0, H1);
    k_bnfinal<<<1, 128>>>(g0, be0);
    k_bnapply<<<(NN * 32 + 255) / 256, 256>>>(H1);

    // --- layer 1 ---
    k_agg<<<NN / 8, 256>>>(H1);
    k_gemm<<<(NN + 127) / 128, 256>>>(H1, Ws1, Wn1, b1, H2);
    k_bnfinal<<<1, 128>>>(g1, be1);
    k_bnapply<<<(NN * 32 + 255) / 256, 256>>>(H2);

    // --- layer 2 (collapsed through the final mean) ---
    k_nodesum<<<(NN + 399) / 400, 128>>>(H2);
    k_final<<<1, 32>>>(Ws2, Wn2, b2, out);
}

// round 5
// speedup vs baseline: 1.3244x; 1.0660x over previous
#include <cuda_runtime.h>
#include <cuda_bf16.h>
#include <math.h>
#include <stdint.h>

#define NN 100000
#define NE 1600000
#define F  128
#define OUTD 32
#define SCAN_B 1024
#define NBLK_SCAN 98   // ceil(100000/1024)

// ---------------- device scratch (no allocations allowed) ----------------
static __device__ int   g_deg[NN];
static __device__ int   g_incl[NN];
static __device__ int   g_bsum[NBLK_SCAN];
static __device__ int   g_rowstart[NN];
static __device__ int   g_cursor[NN];
static __device__ int   g_col[NE];
static __device__ float g_invdeg[NN];
static __device__ float g_cw[NN];          // c[s] = sum over out-edges of invdeg[dst]

static __device__ __nv_bfloat16 g_X0[NN * F];   // features in bf16
static __device__ __nv_bfloat16 g_H1[NN * F];   // layer outputs (pre-BN), bf16
static __device__ __nv_bfloat16 g_H2[NN * F];
static __device__ __nv_bfloat16 g_AGG[NN * F];  // aggregated (post-BN input), bf16

static __device__ float g_colsum[F];
static __device__ float g_colsq[F];
static __device__ float g_scale[F];
static __device__ float g_shift[F];
static __device__ float g_msum[F];
static __device__ float g_wa[F];

// ---------------- helpers ----------------

__device__ __forceinline__ uint32_t f2tf32(float x) {
    uint32_t u;
    asm("cvt.rna.tf32.f32 %0, %1;" : "=r"(u) : "f"(x));
    return u;
}

__device__ __forceinline__ void mma_tf32(float c[4], const uint32_t a[4], const uint32_t b[2]) {
    asm volatile(
        "mma.sync.aligned.m16n8k8.row.col.f32.tf32.tf32.f32 "
        "{%0,%1,%2,%3}, {%4,%5,%6,%7}, {%8,%9}, {%0,%1,%2,%3};"
        : "+f"(c[0]), "+f"(c[1]), "+f"(c[2]), "+f"(c[3])
        : "r"(a[0]), "r"(a[1]), "r"(a[2]), "r"(a[3]), "r"(b[0]), "r"(b[1]));
}

__device__ __forceinline__ float2 bf2f2(uint32_t p) {
    return __bfloat1622float2(*(const __nv_bfloat162*)&p);
}

// ---------------- CSR build ----------------

__global__ void k_zero() {
    int i = blockIdx.x * blockDim.x + threadIdx.x;
    if (i < NN) { g_deg[i] = 0; g_cw[i] = 0.f; }
    if (i < F) {
        g_colsum[i] = 0.f; g_colsq[i] = 0.f;
        g_msum[i]   = 0.f; g_wa[i]    = 0.f;
    }
}

__global__ void k_hist(const int* __restrict__ dst) {
    int e = blockIdx.x * blockDim.x + threadIdx.x;
    if (e < NE) atomicAdd(&g_deg[dst[e]], 1);
}

__global__ void k_scan_block() {
    __shared__ int s[SCAN_B];
    int t = threadIdx.x;
    int i = blockIdx.x * SCAN_B + t;
    int v = (i < NN) ? g_deg[i] : 0;
    s[t] = v;
    __syncthreads();
    for (int off = 1; off < SCAN_B; off <<= 1) {
        int x = (t >= off) ? s[t - off] : 0;
        __syncthreads();
        s[t] += x;
        __syncthreads();
    }
    if (i < NN) g_incl[i] = s[t];
    if (t == SCAN_B - 1) g_bsum[blockIdx.x] = s[t];
}

__global__ void k_scan_top() {   // 1 block, 128 threads: exclusive scan of g_bsum
    __shared__ int ws[4];
    int t = threadIdx.x;
    int lane = t & 31, w = t >> 5;
    int v = (t < NBLK_SCAN) ? g_bsum[t] : 0;
    int x = v;
    #pragma unroll
    for (int off = 1; off < 32; off <<= 1) {
        int y = __shfl_up_sync(0xffffffffu, x, off);
        if (lane >= off) x += y;
    }
    if (lane == 31) ws[w] = x;
    __syncthreads();
    int add = 0;
    #pragma unroll
    for (int i = 0; i < 4; i++) if (i < w) add += ws[i];
    if (t < NBLK_SCAN) g_bsum[t] = x + add - v;   // exclusive
}

__global__ void k_scan_finish() {
    int i = blockIdx.x * blockDim.x + threadIdx.x;
    if (i < NN) {
        int d = g_deg[i];
        int start = g_incl[i] - d + g_bsum[i / SCAN_B];
        g_rowstart[i] = start;
        g_cursor[i]   = start;
        g_invdeg[i]   = 1.0f / (float)max(d, 1);
    }
}

// fused: bucket fill + out-edge weight accumulation
__global__ void k_fillcw(const int* __restrict__ src, const int* __restrict__ dst) {
    int e = blockIdx.x * blockDim.x + threadIdx.x;
    if (e < NE) {
        int d = dst[e];
        int s = src[e];
        int pos = atomicAdd(&g_cursor[d], 1);
        g_col[pos] = s;
        atomicAdd(&g_cw[s], g_invdeg[d]);
    }
}

// features fp32 -> bf16
__global__ void k_x0(const float* __restrict__ feat) {
    int i = blockIdx.x * blockDim.x + threadIdx.x;   // float4 index, NN*32
    float4 v = ((const float4*)feat)[i];
    uint2 o;
    *(__nv_bfloat162*)&o.x = __float22bfloat162_rn(make_float2(v.x, v.y));
    *(__nv_bfloat162*)&o.y = __float22bfloat162_rn(make_float2(v.z, v.w));
    *(uint2*)&g_X0[(size_t)i * 4] = o;
}

// ---------------- aggregation ----------------
// warp-per-node CSR mean aggregation over bf16 rows.
// If BN: input element h -> relu(h*scale + shift) before summing.
template<bool BN>
__global__ void k_agg(const __nv_bfloat16* __restrict__ Hin) {
    int warp = (blockIdx.x * blockDim.x + threadIdx.x) >> 5;
    int lane = threadIdx.x & 31;
    if (warp >= NN) return;
    int c0 = lane * 4;
    float4 sc, sh;
    if (BN) {
        sc = *(const float4*)&g_scale[c0];
        sh = *(const float4*)&g_shift[c0];
    }
    int start = g_rowstart[warp];
    int d     = g_deg[warp];
    float4 acc = make_float4(0.f, 0.f, 0.f, 0.f);

    #define LOADROW(sidx, r01, r23) {                                   \
        uint2 raw = *(const uint2*)(Hin + (size_t)(sidx) * F + c0);     \
        r01 = bf2f2(raw.x); r23 = bf2f2(raw.y);                         \
        if (BN) {                                                        \
            r01.x = fmaxf(r01.x * sc.x + sh.x, 0.f);                     \
            r01.y = fmaxf(r01.y * sc.y + sh.y, 0.f);                     \
            r23.x = fmaxf(r23.x * sc.z + sh.z, 0.f);                     \
            r23.y = fmaxf(r23.y * sc.w + sh.w, 0.f);                     \
        } }

    int j = 0;
    for (; j + 4 <= d; j += 4) {
        int s0 = g_col[start + j];
        int s1 = g_col[start + j + 1];
        int s2 = g_col[start + j + 2];
        int s3 = g_col[start + j + 3];
        float2 a01, a23, b01, b23, c01, c23, d01, d23;
        LOADROW(s0, a01, a23);
        LOADROW(s1, b01, b23);
        LOADROW(s2, c01, c23);
        LOADROW(s3, d01, d23);
        acc.x += (a01.x + b01.x) + (c01.x + d01.x);
        acc.y += (a01.y + b01.y) + (c01.y + d01.y);
        acc.z += (a23.x + b23.x) + (c23.x + d23.x);
        acc.w += (a23.y + b23.y) + (c23.y + d23.y);
    }
    for (; j < d; j++) {
        int s = g_col[start + j];
        float2 a01, a23;
        LOADROW(s, a01, a23);
        acc.x += a01.x; acc.y += a01.y; acc.z += a23.x; acc.w += a23.y;
    }
    #undef LOADROW

    float w = g_invdeg[warp];
    uint2 o;
    *(__nv_bfloat162*)&o.x = __float22bfloat162_rn(make_float2(acc.x * w, acc.y * w));
    *(__nv_bfloat162*)&o.y = __float22bfloat162_rn(make_float2(acc.z * w, acc.w * w));
    *(uint2*)&g_AGG[(size_t)warp * F + c0] = o;
}

// ---------------- tf32 tensor-core GEMM ----------------
// Hout = relu([Xbn | AGG] @ [Ws;Wn] + b) stored bf16, fused BN-stat accumulation.
// If BN: the self half (k<128) applies relu(x*scale+shift) at load (AGG half is
// already BN-applied by k_agg).

#define AS_LD 36
#define BS_LD 136

template<bool BN>
__global__ __launch_bounds__(256) void k_gemm(
    const __nv_bfloat16* __restrict__ X,
    const float* __restrict__ Ws,
    const float* __restrict__ Wn,
    const float* __restrict__ bias,
    __nv_bfloat16* __restrict__ Hout)
{
    __shared__ float As[128 * AS_LD];   // m-major, tf32 bits
    __shared__ float Bs[32 * BS_LD];    // k-major, tf32 bits
    __shared__ float sColS[128];
    __shared__ float sColQ[128];

    int tid  = threadIdx.x;
    int lane = tid & 31;
    int wid  = tid >> 5;
    int warp_m = wid >> 1;         // 0..3
    int warp_n = wid & 1;          // 0..1
    int g  = lane >> 2;            // 0..7
    int tg = lane & 3;             // 0..3
    int row0 = blockIdx.x * 128;

    if (tid < 128) { sColS[tid] = 0.f; sColQ[tid] = 0.f; }

    float c[2][8][4];
    #pragma unroll
    for (int mt = 0; mt < 2; mt++)
        #pragma unroll
        for (int nt = 0; nt < 8; nt++)
            #pragma unroll
            for (int r = 0; r < 4; r++) c[mt][nt][r] = 0.f;

    const uint32_t* Asu = (const uint32_t*)As;
    const uint32_t* Bsu = (const uint32_t*)Bs;

    for (int kc = 0; kc < 8; kc++) {
        // ---- load A tile: rows row0..+127, k-cols kc*32..+31 of [Xbn|AGG] (bf16) ----
        #pragma unroll
        for (int p = 0; p < 4; p++) {
            int id   = tid + p * 256;       // 0..1023 4-elem slots
            int arow = id >> 3;
            int ac4  = id & 7;
            int kg   = kc * 32 + ac4 * 4;
            int grow = row0 + arow;
            float4 av = make_float4(0.f, 0.f, 0.f, 0.f);
            if (grow < NN) {
                const __nv_bfloat16* base = (kg < 128)
                    ? (X + (size_t)grow * F + kg)
                    : (g_AGG + (size_t)grow * F + (kg - 128));
                uint2 raw = *(const uint2*)base;
                float2 f01 = bf2f2(raw.x);
                float2 f23 = bf2f2(raw.y);
                av = make_float4(f01.x, f01.y, f23.x, f23.y);
                if (BN && kg < 128) {
                    float4 sc = *(const float4*)&g_scale[kg];
                    float4 sh = *(const float4*)&g_shift[kg];
                    av.x = fmaxf(av.x * sc.x + sh.x, 0.f);
                    av.y = fmaxf(av.y * sc.y + sh.y, 0.f);
                    av.z = fmaxf(av.z * sc.z + sh.z, 0.f);
                    av.w = fmaxf(av.w * sc.w + sh.w, 0.f);
                }
            }
            uint4 tv;
            tv.x = f2tf32(av.x); tv.y = f2tf32(av.y);
            tv.z = f2tf32(av.z); tv.w = f2tf32(av.w);
            *(uint4*)&As[arow * AS_LD + ac4 * 4] = tv;
        }
        // ---- load B tile: k-rows kc*32..+31, n-cols 0..127 of [Ws;Wn] (fp32) ----
        #pragma unroll
        for (int p = 0; p < 4; p++) {
            int id  = tid + p * 256;
            int bk  = id >> 5;              // 0..31 local k
            int bn4 = id & 31;              // float4 col group
            int kg  = kc * 32 + bk;
            const float* base = (kg < 128) ? (Ws + (size_t)kg * 128 + bn4 * 4)
                                           : (Wn + (size_t)(kg - 128) * 128 + bn4 * 4);
            float4 wv = *(const float4*)base;
            uint4 tv;
            tv.x = f2tf32(wv.x); tv.y = f2tf32(wv.y);
            tv.z = f2tf32(wv.z); tv.w = f2tf32(wv.w);
            *(uint4*)&Bs[bk * BS_LD + bn4 * 4] = tv;
        }
        __syncthreads();

        #pragma unroll
        for (int ks = 0; ks < 4; ks++) {
            int k0 = ks * 8;
            uint32_t a[2][4];
            #pragma unroll
            for (int mt = 0; mt < 2; mt++) {
                int bm = warp_m * 32 + mt * 16;
                a[mt][0] = Asu[(bm + g) * AS_LD + k0 + tg];
                a[mt][1] = Asu[(bm + g + 8) * AS_LD + k0 + tg];
                a[mt][2] = Asu[(bm + g) * AS_LD + k0 + tg + 4];
                a[mt][3] = Asu[(bm + g + 8) * AS_LD + k0 + tg + 4];
            }
            uint32_t b[8][2];
            #pragma unroll
            for (int nt = 0; nt < 8; nt++) {
                int bn = warp_n * 64 + nt * 8 + g;
                b[nt][0] = Bsu[(k0 + tg) * BS_LD + bn];
                b[nt][1] = Bsu[(k0 + tg + 4) * BS_LD + bn];
            }
            #pragma unroll
            for (int mt = 0; mt < 2; mt++)
                #pragma unroll
                for (int nt = 0; nt < 8; nt++)
                    mma_tf32(c[mt][nt], a[mt], b[nt]);
        }
        __syncthreads();
    }

    // ---- epilogue: bias + relu + bf16 store + BN stats ----
    #pragma unroll
    for (int mt = 0; mt < 2; mt++) {
        int rA = row0 + warp_m * 32 + mt * 16 + g;
        int rB = rA + 8;
        bool vA = rA < NN, vB = rB < NN;
        #pragma unroll
        for (int nt = 0; nt < 8; nt++) {
            int col = warp_n * 64 + nt * 8 + tg * 2;
            float2 bb = *(const float2*)&bias[col];
            float v0 = fmaxf(c[mt][nt][0] + bb.x, 0.f);
            float v1 = fmaxf(c[mt][nt][1] + bb.y, 0.f);
            float v2 = fmaxf(c[mt][nt][2] + bb.x, 0.f);
            float v3 = fmaxf(c[mt][nt][3] + bb.y, 0.f);
            float s0 = 0.f, s1 = 0.f, q0 = 0.f, q1 = 0.f;
            if (vA) {
                *(__nv_bfloat162*)&Hout[(size_t)rA * F + col] =
                    __float22bfloat162_rn(make_float2(v0, v1));
                s0 += v0; q0 += v0 * v0; s1 += v1; q1 += v1 * v1;
            }
            if (vB) {
                *(__nv_bfloat162*)&Hout[(size_t)rB * F + col] =
                    __float22bfloat162_rn(make_float2(v2, v3));
                s0 += v2; q0 += v2 * v2; s1 += v3; q1 += v3 * v3;
            }
            atomicAdd(&sColS[col], s0);
            atomicAdd(&sColS[col + 1], s1);
            atomicAdd(&sColQ[col], q0);
            atomicAdd(&sColQ[col + 1], q1);
        }
    }
    __syncthreads();
    if (tid < 128) {
        atomicAdd(&g_colsum[tid], sColS[tid]);
        atomicAdd(&g_colsq[tid],  sColQ[tid]);
    }
}

// ---------------- BN coefficients ----------------

__global__ void k_bnfinal(const float* __restrict__ g, const float* __restrict__ be) {
    int t = threadIdx.x;
    if (t < F) {
        float inv_n = 1.0f / (float)NN;
        float mu  = g_colsum[t] * inv_n;
        float var = g_colsq[t] * inv_n - mu * mu;
        float sc  = g[t] * rsqrtf(var + 1e-5f);
        g_scale[t] = sc;
        g_shift[t] = be[t] - mu * sc;
        g_colsum[t] = 0.f;   // ready for next gemm
        g_colsq[t]  = 0.f;
    }
}

// ---------------- final collapsed layer-2 ----------------
// H2 (bf16, pre-BN): apply BN1+relu at load.
// msum += column sums ; wa += sum_s cw[s] * h
#define NS_ROWS 400
__global__ void k_nodesum(const __nv_bfloat16* __restrict__ H) {
    __shared__ float sm[128], sw[128];
    int t = threadIdx.x;            // 256 threads
    if (t < 128) { sm[t] = 0.f; sw[t] = 0.f; }
    __syncthreads();
    int pc   = t & 63;              // pair-col: cols 2pc, 2pc+1
    int rsub = t >> 6;              // 0..3
    int c0 = pc * 2;
    float2 sc = *(const float2*)&g_scale[c0];
    float2 sh = *(const float2*)&g_shift[c0];
    int r0 = blockIdx.x * NS_ROWS;
    float s0 = 0.f, s1 = 0.f, w0 = 0.f, w1 = 0.f;
    for (int r = rsub; r < NS_ROWS; r += 4) {
        int row = r0 + r;
        if (row < NN) {
            uint32_t raw = *(const uint32_t*)&H[(size_t)row * F + c0];
            float2 f = bf2f2(raw);
            f.x = fmaxf(f.x * sc.x + sh.x, 0.f);
            f.y = fmaxf(f.y * sc.y + sh.y, 0.f);
            float cw = g_cw[row];
            s0 += f.x; s1 += f.y;
            w0 += cw * f.x; w1 += cw * f.y;
        }
    }
    atomicAdd(&sm[c0], s0);     atomicAdd(&sm[c0 + 1], s1);
    atomicAdd(&sw[c0], w0);     atomicAdd(&sw[c0 + 1], w1);
    __syncthreads();
    if (t < 128) {
        atomicAdd(&g_msum[t], sm[t]);
        atomicAdd(&g_wa[t],   sw[t]);
    }
}

// hg = (msum/N)@Ws2 + (wa/N)@Wn2 + b2 ; out = softmax(hg)
__global__ void k_final(const float* __restrict__ Ws2, const float* __restrict__ Wn2,
                        const float* __restrict__ b2, float* __restrict__ out) {
    int j = threadIdx.x;  // 0..31
    float inv_n = 1.0f / (float)NN;
    float acc = b2[j];
    for (int k = 0; k < 128; k++) {
        acc += (g_msum[k] * inv_n) * Ws2[k * 32 + j]
             + (g_wa[k]   * inv_n) * Wn2[k * 32 + j];
    }
    float m = acc;
    #pragma unroll
    for (int off = 16; off > 0; off >>= 1)
        m = fmaxf(m, __shfl_xor_sync(0xffffffffu, m, off));
    float e = expf(acc - m);
    float s = e;
    #pragma unroll
    for (int off = 16; off > 0; off >>= 1)
        s += __shfl_xor_sync(0xffffffffu, s, off);
    out[j] = e / s;
}

// ---------------- host ----------------

extern "C" void kernel_launch(void* const* d_in, const int* in_sizes, int n_in,
                              void* d_out, int out_size) {
    const float* features = (const float*)d_in[0];
    const int*   src      = (const int*)  d_in[1];
    const int*   dst      = (const int*)  d_in[2];
    const float* Ws0 = (const float*)d_in[3];
    const float* Wn0 = (const float*)d_in[4];
    const float* b0  = (const float*)d_in[5];
    const float* Ws1 = (const float*)d_in[6];
    const float* Wn1 = (const float*)d_in[7];
    const float* b1  = (const float*)d_in[8];
    const float* Ws2 = (const float*)d_in[9];
    const float* Wn2 = (const float*)d_in[10];
    const float* b2  = (const float*)d_in[11];
    const float* g0  = (const float*)d_in[12];
    const float* be0 = (const float*)d_in[13];
    const float* g1  = (const float*)d_in[14];
    const float* be1 = (const float*)d_in[15];
    float* out = (float*)d_out;

    __nv_bfloat16* X0 = nullptr; cudaGetSymbolAddress((void**)&X0, g_X0);
    __nv_bfloat16* H1 = nullptr; cudaGetSymbolAddress((void**)&H1, g_H1);
    __nv_bfloat16* H2 = nullptr; cudaGetSymbolAddress((void**)&H2, g_H2);

    // --- prep: CSR build + feature conversion + zero accumulators ---
    k_zero<<<(NN + 255) / 256, 256>>>();
    k_hist<<<NE / 256, 256>>>(dst);
    k_x0<<<NN * 32 / 256, 256>>>(features);
    k_scan_block<<<NBLK_SCAN, SCAN_B>>>();
    k_scan_top<<<1, 128>>>();
    k_scan_finish<<<(NN + 255) / 256, 256>>>();
    k_fillcw<<<NE / 256, 256>>>(src, dst);

    // --- layer 0 ---
    k_agg<false><<<NN / 8, 256>>>(X0);
    k_gemm<false><<<(NN + 127) / 128, 256>>>(X0, Ws0, Wn0, b0, H1);
    k_bnfinal<<<1, 128>>>(g0, be0);

    // --- layer 1 (BN of layer 0 fused into loads) ---
    k_agg<true><<<NN / 8, 256>>>(H1);
    k_gemm<true><<<(NN + 127) / 128, 256>>>(H1, Ws1, Wn1, b1, H2);
    k_bnfinal<<<1, 128>>>(g1, be1);

    // --- layer 2 (collapsed through the final mean; BN1 fused into load) ---
    k_nodesum<<<(NN + NS_ROWS - 1) / NS_ROWS, 256>>>(H2);
    k_final<<<1, 32>>>(Ws2, Wn2, b2, out);
}